// round 14
// baseline (speedup 1.0000x reference)
#include <cuda_runtime.h>
#include <cuda_fp16.h>
#include <math.h>

typedef unsigned int u32;

#define NRAYS 8192
#define NVOX  100000

__device__ float g_sigma[NRAYS * 64];
__device__ float g_rgb[NRAYS * 64 * 3];
__device__ float g_cv[NRAYS * 64];
__device__ int   g_chunks[NRAYS * 2];
__device__ int   g_nchunks;
__device__ float g_Wfc[128 * 64];   // Wfeat @ Wc1[:128]  (fused feat+color weight)
__device__ float g_cvc[64];         // bc1 + bfeat @ Wc1[:128]

// pre-packed B fragments: per (ks, nc, lane) a uint4 {b0h, b1h, b0l, b1l} (fp16 pairs)
__device__ uint4 g_fW1[2 * 16 * 32];    // 32->128
__device__ uint4 g_fW2[8 * 16 * 32];    // 128->128
__device__ uint4 g_fWC[8 * 8 * 32];     // 128->64 (fused Wfc)

__device__ __forceinline__ u32 sa(const void* p) {
    return (u32)__cvta_generic_to_shared(p);
}
__device__ __forceinline__ void ldsm4(u32* r, u32 addr) {
    asm volatile("ldmatrix.sync.aligned.m8n8.x4.shared.b16 {%0,%1,%2,%3}, [%4];"
        : "=r"(r[0]), "=r"(r[1]), "=r"(r[2]), "=r"(r[3]) : "r"(addr));
}
__device__ __forceinline__ void mma16816(float* d, const u32* a, const u32* b) {
    asm volatile(
        "mma.sync.aligned.m16n8k16.row.col.f32.f16.f16.f32 "
        "{%0,%1,%2,%3}, {%4,%5,%6,%7}, {%8,%9}, {%0,%1,%2,%3};"
        : "+f"(d[0]), "+f"(d[1]), "+f"(d[2]), "+f"(d[3])
        : "r"(a[0]), "r"(a[1]), "r"(a[2]), "r"(a[3]), "r"(b[0]), "r"(b[1]));
}
__device__ __forceinline__ u32 pkhf(float lo, float hi) {   // low half = lo
    u32 r;
    asm("{\n\t.reg .b16 h0, h1;\n\t"
        "cvt.rn.f16.f32 h0, %1;\n\t"
        "cvt.rn.f16.f32 h1, %2;\n\t"
        "mov.b32 %0, {h0, h1};\n\t}"
        : "=r"(r) : "f"(lo), "f"(hi));
    return r;
}

// M=64 MMA layer: A (fp16 plane, swizzled rows, byte stride astride) x prepacked B
// frags (hi+lo). acc layout: [mt*NCW + c][4], mt = 0..3 (16-row tiles).
template<int KS, int NCW>
__device__ __forceinline__ void do_layer64(u32 aP, int astride,
                                           const uint4* __restrict__ frag,
                                           int NCtot, int ncg0, int lane, float* acc)
{
    const int rit = (lane & 7) | (lane & 8);
    const int half = lane >> 4;
#pragma unroll
    for (int ks = 0; ks < KS; ks++) {
        const int u = ks * 2 + half;
        u32 a[4][4];
#pragma unroll
        for (int mt = 0; mt < 4; mt++) {
            const int r = mt * 16 + rit;
            ldsm4(a[mt], aP + r * astride + ((u ^ (r & 7)) << 4));
        }
#pragma unroll
        for (int c = 0; c < NCW; c++) {
            uint4 f = frag[(ks * NCtot + ncg0 + c) * 32 + lane];
            u32 bh[2] = {f.x, f.y}, bl[2] = {f.z, f.w};
#pragma unroll
            for (int mt = 0; mt < 4; mt++) {
                mma16816(acc + (mt * NCW + c) * 4, a[mt], bh);
                mma16816(acc + (mt * NCW + c) * 4, a[mt], bl);
            }
        }
    }
}

// epilogue: bias (+relu) (+sigma partials), fp16 pack, swizzled store, 64 rows
template<int NCW, bool RELU, bool SIG>
__device__ __forceinline__ void epi_act64(const float* acc, int ncg0,
                                          const float* __restrict__ bias,
                                          char* outP, int lane,
                                          const float* __restrict__ wsg, float* srow)
{
    const int g = lane >> 2, tq = lane & 3;
#pragma unroll
    for (int mt = 0; mt < 4; mt++) {
#pragma unroll
        for (int c = 0; c < NCW; c++) {
            const int ncg = ncg0 + c;
            const int c0 = ncg * 8 + 2 * tq;
            const float* a = acc + (mt * NCW + c) * 4;
            float x0 = a[0] + bias[c0], x1 = a[1] + bias[c0 + 1];
            float x2 = a[2] + bias[c0], x3 = a[3] + bias[c0 + 1];
            if (RELU) {
                x0 = fmaxf(x0, 0.f); x1 = fmaxf(x1, 0.f);
                x2 = fmaxf(x2, 0.f); x3 = fmaxf(x3, 0.f);
            }
            if (SIG) {
                srow[mt * 2 + 0] += x0 * wsg[c0] + x1 * wsg[c0 + 1];
                srow[mt * 2 + 1] += x2 * wsg[c0] + x3 * wsg[c0 + 1];
            }
            const int off0 = (mt * 16 + g) * 256 + ((ncg ^ g) << 4) + 4 * tq;
            const int off1 = (mt * 16 + g + 8) * 256 + ((ncg ^ g) << 4) + 4 * tq;
            *(u32*)(outP + off0) = pkhf(x0, x1);
            *(u32*)(outP + off1) = pkhf(x2, x3);
        }
    }
}

__global__ void __launch_bounds__(128, 4)
mlp_kernel(const float* __restrict__ pts, const int* __restrict__ p2v,
           const float* __restrict__ vox_emb, const float* __restrict__ Wpts,
           const float* __restrict__ b1, const float* __restrict__ b2,
           const float* __restrict__ Wsig, const float* __restrict__ bsig,
           const float* __restrict__ Wc2, const float* __restrict__ bc2)
{
    const int n = g_nchunks;
    const int tile = blockIdx.x;
    if (2 * tile >= n) return;
    const int cA = g_chunks[2 * tile];
    const int cB = (2 * tile + 1 < n) ? g_chunks[2 * tile + 1] : cA;
    const int gA0 = (cA >> 1) * 64 + (cA & 1) * 32;   // first sample index of chunk A
    const int gB0 = (cB >> 1) * 64 + (cB & 1) * 32;

    const int t = threadIdx.x;
    const int w = t >> 5, lane = t & 31;
    const int g = lane >> 2, tq = lane & 3;

    // veP (64 rows x 128B = 8KB) aliases the front of bufB: ve's last reader is the
    // L1-layer MMA pass; bufB is first written by the L2 epilogue (after a sync).
    __shared__ __align__(16) char bufA[16384];   // 64 rows x 256B (fp16, 128 cols)
    __shared__ __align__(16) char bufB[16384];
    char* const veP = bufB;
    __shared__ float cv_sh[128];                 // [rayA cv(64) | rayB cv(64)]
    __shared__ float b1s[128], b2s[128], wsg[128], wc2s[192], wps[96];
    __shared__ float bc2s[3], bsgs;
    __shared__ float sigp[4 * 64];
    __shared__ float rgbp[4 * 64 * 3];
    __shared__ int   idx_sh[64];
    __shared__ float pAs[96], pBs[96];

    if (t < 128) { b1s[t] = b1[t]; b2s[t] = b2[t]; wsg[t] = Wsig[t]; }
    if (t < 96) { wps[t] = Wpts[t]; pAs[t] = pts[gA0 * 3 + t]; pBs[t] = pts[gB0 * 3 + t]; }
    if (t < 64) { wc2s[t] = Wc2[t]; wc2s[64 + t] = Wc2[64 + t]; wc2s[128 + t] = Wc2[128 + t]; }
    if (t < 64) idx_sh[t] = (t < 32) ? p2v[gA0 + t] : p2v[gB0 + t - 32];
    if (t < 128) cv_sh[t] = g_cv[((t < 64) ? (cA >> 1) : (cB >> 1)) * 64 + (t & 63)];
    if (t == 0) { bsgs = bsig[0]; bc2s[0] = bc2[0]; bc2s[1] = bc2[1]; bc2s[2] = bc2[2]; }
    __syncthreads();

    // ---- build ve: 64 rows (A: 0-31, B: 32-63), fp16, swizzled ----
    {
#pragma unroll
        for (int pass = 0; pass < 2; pass++) {
            const int e = pass * 128 + t;          // e in [0,256): (row, q)
            const int row = e >> 2, q = e & 3;
            const int vi0 = idx_sh[row];
            const int vi = vi0 < 0 ? 0 : vi0;
            const float* ps = (row < 32) ? (pAs + row * 3) : (pBs + (row - 32) * 3);
            const float px = ps[0], py = ps[1], pz = ps[2];
            const float4* v4 = (const float4*)(vox_emb + (size_t)vi * 32 + q * 8);
            u32 hw[4];
#pragma unroll
            for (int i = 0; i < 2; i++) {
                float4 v = v4[i];
                const int k = q * 8 + i * 4;
                float x0 = v.x + px * wps[k]     + py * wps[32 + k]     + pz * wps[64 + k];
                float x1 = v.y + px * wps[k + 1] + py * wps[32 + k + 1] + pz * wps[64 + k + 1];
                float x2 = v.z + px * wps[k + 2] + py * wps[32 + k + 2] + pz * wps[64 + k + 2];
                float x3 = v.w + px * wps[k + 3] + py * wps[32 + k + 3] + pz * wps[64 + k + 3];
                hw[2 * i]     = pkhf(x0, x1);
                hw[2 * i + 1] = pkhf(x2, x3);
            }
            const int off = row * 128 + ((q ^ (row & 7)) << 4);
            *(uint4*)(veP + off) = make_uint4(hw[0], hw[1], hw[2], hw[3]);
        }
    }
    __syncthreads();

    const u32 veS = sa(veP);
    const u32 bAS = sa(bufA);
    const u32 bBS = sa(bufB);

    float acc[64];

    // ---- L1: 32 -> 128, relu ----
#pragma unroll
    for (int i = 0; i < 64; i++) acc[i] = 0.f;
    do_layer64<2, 4>(veS, 128, g_fW1, 16, 4 * w, lane, acc);
    epi_act64<4, true, false>(acc, 4 * w, b1s, bufA, lane, wsg, nullptr);
    __syncthreads();

    // ---- L2: 128 -> 128, relu, + sigma partials ----
#pragma unroll
    for (int i = 0; i < 64; i++) acc[i] = 0.f;
    do_layer64<8, 4>(bAS, 256, g_fW2, 16, 4 * w, lane, acc);
    {
        float srow[8] = {0.f, 0.f, 0.f, 0.f, 0.f, 0.f, 0.f, 0.f};
        epi_act64<4, true, true>(acc, 4 * w, b2s, bufB, lane, wsg, srow);
#pragma unroll
        for (int i = 0; i < 8; i++) {
            srow[i] += __shfl_xor_sync(0xffffffffu, srow[i], 1);
            srow[i] += __shfl_xor_sync(0xffffffffu, srow[i], 2);
        }
        if (tq == 0) {
#pragma unroll
            for (int mt = 0; mt < 4; mt++) {
                sigp[w * 64 + mt * 16 + g]     = srow[mt * 2 + 0];
                sigp[w * 64 + mt * 16 + 8 + g] = srow[mt * 2 + 1];
            }
        }
    }
    __syncthreads();
    if (t < 64) {
        const float s = sigp[t] + sigp[64 + t] + sigp[128 + t] + sigp[192 + t] + bsgs;
        const int gi = (t < 32) ? (gA0 + t) : (gB0 + t - 32);
        g_sigma[gi] = s;
    }

    // ---- fused feat+color: h(bufB) @ Wfc -> 64 (+cv', relu), then rgb = c @ Wc2 ----
#pragma unroll
    for (int i = 0; i < 32; i++) acc[i] = 0.f;
    do_layer64<8, 2>(bBS, 256, g_fWC, 8, 2 * w, lane, acc);
    {
        float rr[24];
#pragma unroll
        for (int i = 0; i < 24; i++) rr[i] = 0.f;
#pragma unroll
        for (int mt = 0; mt < 4; mt++) {
            const int cvb = (mt >= 2) ? 64 : 0;   // rows 0-31 -> rayA, 32-63 -> rayB
#pragma unroll
            for (int c = 0; c < 2; c++) {
                const int ncg = 2 * w + c;
                const int c0 = ncg * 8 + 2 * tq;
                const float* a = acc + (mt * 2 + c) * 4;
                float x0 = fmaxf(a[0] + cv_sh[cvb + c0], 0.f);
                float x1 = fmaxf(a[1] + cv_sh[cvb + c0 + 1], 0.f);
                float x2 = fmaxf(a[2] + cv_sh[cvb + c0], 0.f);
                float x3 = fmaxf(a[3] + cv_sh[cvb + c0 + 1], 0.f);
#pragma unroll
                for (int ch = 0; ch < 3; ch++) {
                    rr[(mt * 2 + 0) * 3 + ch] += x0 * wc2s[c0 * 3 + ch] + x1 * wc2s[(c0 + 1) * 3 + ch];
                    rr[(mt * 2 + 1) * 3 + ch] += x2 * wc2s[c0 * 3 + ch] + x3 * wc2s[(c0 + 1) * 3 + ch];
                }
            }
        }
#pragma unroll
        for (int i = 0; i < 24; i++) {
            rr[i] += __shfl_xor_sync(0xffffffffu, rr[i], 1);
            rr[i] += __shfl_xor_sync(0xffffffffu, rr[i], 2);
        }
        if (tq == 0) {
#pragma unroll
            for (int mt = 0; mt < 4; mt++) {
                const int r0 = mt * 16 + g, r1 = mt * 16 + 8 + g;
#pragma unroll
                for (int ch = 0; ch < 3; ch++) {
                    rgbp[w * 192 + r0 * 3 + ch] = rr[(mt * 2 + 0) * 3 + ch];
                    rgbp[w * 192 + r1 * 3 + ch] = rr[(mt * 2 + 1) * 3 + ch];
                }
            }
        }
    }
    __syncthreads();
    {
        for (int e = t; e < 192; e += 128) {
            const int row = e / 3, ch = e - row * 3;
            const float v = rgbp[row * 3 + ch] + rgbp[192 + row * 3 + ch]
                          + rgbp[384 + row * 3 + ch] + rgbp[576 + row * 3 + ch] + bc2s[ch];
            const int gi = (row < 32) ? (gA0 + row) : (gB0 + row - 32);
            g_rgb[gi * 3 + ch] = v;
        }
    }
}

// fuse feat into color: Wfc = Wfeat @ Wc1[:128]  and  g_cvc = bc1 + bfeat @ Wc1[:128]
__global__ void wfc_kernel(const float* __restrict__ Wfeat, const float* __restrict__ Wc1,
                           const float* __restrict__ bfeat, const float* __restrict__ bc1)
{
    const int e = blockIdx.x * 256 + threadIdx.x;
    if (e < 8192) {
        const int k = e >> 6, n = e & 63;
        float s = 0.f;
#pragma unroll 8
        for (int j = 0; j < 128; j++) s += Wfeat[k * 128 + j] * Wc1[j * 64 + n];
        g_Wfc[k * 64 + n] = s;
    } else if (e < 8256) {
        const int n = e - 8192;
        float s = bc1[n];
#pragma unroll 8
        for (int j = 0; j < 128; j++) s += bfeat[j] * Wc1[j * 64 + n];
        g_cvc[n] = s;
    }
}

// per-ray view PE -> cv[ray][64] = g_cvc + vemb @ Wc1[128:155]; 4 rays per block.
// Also builds the chunk worklist (one chunk per 32-sample half whose first sample
// is valid — valid is a prefix). pack_kernel resets g_nchunks and runs before this.
__global__ void __launch_bounds__(256)
prep_kernel(const float* __restrict__ rays_d, const float* __restrict__ Wc1,
            const int* __restrict__ p2v)
{
    __shared__ float ve[4][27];
    const int t = threadIdx.x;
    const int r = t >> 6, col = t & 63;
    const int ray = blockIdx.x * 4 + r;
    if (col == 0) {
        if (p2v[ray * 64] >= 0)      { int i = atomicAdd(&g_nchunks, 1); g_chunks[i] = ray * 2; }
        if (p2v[ray * 64 + 32] >= 0) { int i = atomicAdd(&g_nchunks, 1); g_chunks[i] = ray * 2 + 1; }
    }
    if (col < 27) {
        float dx = rays_d[ray * 3 + 0], dy = rays_d[ray * 3 + 1], dz = rays_d[ray * 3 + 2];
        float v;
        if (col == 0) v = dx;
        else if (col == 1) v = dy;
        else if (col == 2) v = dz;
        else {
            int u = col - 3;
            bool isc = (u >= 12);
            if (isc) u -= 12;
            int i = u >> 2, l = u & 3;
            float di = (i == 0) ? dx : ((i == 1) ? dy : dz);
            float a = di * (float)(1 << l);
            v = isc ? __cosf(a) : __sinf(a);   // |a| <= 8: intrinsic abs err ~1e-5
        }
        ve[r][col] = v;
    }
    __syncthreads();
    float s = g_cvc[col];
#pragma unroll
    for (int k = 0; k < 27; k++) s += Wc1[(128 + k) * 64 + col] * ve[r][k];
    g_cv[ray * 64 + col] = s;
}

// pack weight fragments (fp16 hi/lo) into mma B-operand order; also resets g_nchunks
__global__ void pack_kernel(const float* __restrict__ W1, const float* __restrict__ W2)
{
    int e = blockIdx.x * 256 + threadIdx.x;
    if (e == 7168) { g_nchunks = 0; return; }
    const float* W;
    uint4* dst;
    int N, NCtot, idx;
    if (e < 1024)      { W = W1;    dst = g_fW1; N = 128; NCtot = 16; idx = e; }
    else if (e < 5120) { W = W2;    dst = g_fW2; N = 128; NCtot = 16; idx = e - 1024; }
    else if (e < 7168) { W = g_Wfc; dst = g_fWC; N = 64;  NCtot = 8;  idx = e - 5120; }
    else return;
    const int lane = idx & 31;
    const int nc = (idx >> 5) % NCtot;
    const int ks = idx / (32 * NCtot);
    const int n = nc * 8 + (lane >> 2);
    const int k0 = ks * 16 + 2 * (lane & 3);
    float w00 = W[k0 * N + n], w01 = W[(k0 + 1) * N + n];
    float w08 = W[(k0 + 8) * N + n], w09 = W[(k0 + 9) * N + n];
    __half h00 = __float2half_rn(w00), h01 = __float2half_rn(w01);
    __half h08 = __float2half_rn(w08), h09 = __float2half_rn(w09);
    u32 b0h = ((u32)__half_as_ushort(h01) << 16) | __half_as_ushort(h00);
    u32 b1h = ((u32)__half_as_ushort(h09) << 16) | __half_as_ushort(h08);
    u32 b0l = pkhf(w00 - __half2float(h00), w01 - __half2float(h01));
    u32 b1l = pkhf(w08 - __half2float(h08), w09 - __half2float(h09));
    dst[idx] = make_uint4(b0h, b1h, b0l, b1l);
}

// per-ray volumetric rendering: warp per ray, 2 samples per lane
__global__ void __launch_bounds__(256)
render_kernel(const float* __restrict__ t_vals, const float* __restrict__ dists,
              const int* __restrict__ p2v, float* __restrict__ out)
{
    int warp = threadIdx.x >> 5;
    int lane = threadIdx.x & 31;
    int ray = blockIdx.x * 8 + warp;
    if (ray >= NRAYS) return;
    int b = ray * 64;
    int i1 = b + lane, i2 = b + 32 + lane;

    bool m1 = p2v[i1] >= 0;
    bool m2 = p2v[i2] >= 0;
    float fe1 = m1 ? fmaxf(g_sigma[i1], 0.f) * dists[i1] : 0.f;
    float fe2 = m2 ? fmaxf(g_sigma[i2], 0.f) * dists[i2] : 0.f;

    float c1 = fe1;
#pragma unroll
    for (int d = 1; d < 32; d <<= 1) {
        float v = __shfl_up_sync(0xffffffffu, c1, d);
        if (lane >= d) c1 += v;
    }
    float tot = __shfl_sync(0xffffffffu, c1, 31);
    float c2 = fe2;
#pragma unroll
    for (int d = 1; d < 32; d <<= 1) {
        float v = __shfl_up_sync(0xffffffffu, c2, d);
        if (lane >= d) c2 += v;
    }
    c2 += tot;

    float T1 = expf(-(c1 - fe1));
    float T2 = expf(-(c2 - fe2));
    float w1 = (1.f - expf(-fe1)) * T1;
    float w2 = (1.f - expf(-fe2)) * T2;

    float r = 0.f, g = 0.f, bl = 0.f;
    if (m1) {
        float x = g_rgb[i1 * 3 + 0], y = g_rgb[i1 * 3 + 1], z = g_rgb[i1 * 3 + 2];
        r += w1 * (0.5f * x + 0.5f);
        g += w1 * (0.5f * y + 0.5f);
        bl += w1 * (0.5f * z + 0.5f);
    }
    if (m2) {
        float x = g_rgb[i2 * 3 + 0], y = g_rgb[i2 * 3 + 1], z = g_rgb[i2 * 3 + 2];
        r += w2 * (0.5f * x + 0.5f);
        g += w2 * (0.5f * y + 0.5f);
        bl += w2 * (0.5f * z + 0.5f);
    }
    float aw = w1 + w2;
    float dp = w1 * t_vals[i1] + w2 * t_vals[i2];

#pragma unroll
    for (int d = 16; d; d >>= 1) {
        r  += __shfl_down_sync(0xffffffffu, r, d);
        g  += __shfl_down_sync(0xffffffffu, g, d);
        bl += __shfl_down_sync(0xffffffffu, bl, d);
        aw += __shfl_down_sync(0xffffffffu, aw, d);
        dp += __shfl_down_sync(0xffffffffu, dp, d);
    }
    if (lane == 0) {
        bool hit = p2v[b] >= 0;
        float disp = hit ? 1.f / fmaxf(1e-10f, dp / fmaxf(aw, 1e-10f)) : 0.f;
        out[ray * 3 + 0] = hit ? r : 0.f;
        out[ray * 3 + 1] = hit ? g : 0.f;
        out[ray * 3 + 2] = hit ? bl : 0.f;
        out[NRAYS * 3 + ray] = disp;
        out[NRAYS * 4 + ray] = hit ? aw : 0.f;
    }
}

extern "C" void kernel_launch(void* const* d_in, const int* in_sizes, int n_in,
                              void* d_out, int out_size)
{
    const float* rays_d = (const float*)d_in[0];
    const float* pts    = (const float*)d_in[1];
    const float* t_vals = (const float*)d_in[2];
    const float* dists  = (const float*)d_in[3];
    const int* p2v;
    const float *vox, *Wpts, *W1, *b1, *W2, *b2, *Wsig, *bsig, *Wfeat, *bfeat,
                *Wc1, *bc1, *Wc2, *bc2;

    if (in_sizes[4] == NVOX * 32) {
        vox   = (const float*)d_in[4];
        Wpts  = (const float*)d_in[5];
        W1    = (const float*)d_in[6];
        b1    = (const float*)d_in[7];
        W2    = (const float*)d_in[8];
        b2    = (const float*)d_in[9];
        Wsig  = (const float*)d_in[10];
        bsig  = (const float*)d_in[11];
        Wfeat = (const float*)d_in[12];
        bfeat = (const float*)d_in[13];
        Wc1   = (const float*)d_in[14];
        bc1   = (const float*)d_in[15];
        Wc2   = (const float*)d_in[16];
        bc2   = (const float*)d_in[17];
        p2v   = (const int*)d_in[18];
    } else {
        p2v   = (const int*)d_in[4];
        vox   = (const float*)d_in[6];
        Wpts  = (const float*)d_in[7];
        W1    = (const float*)d_in[8];
        b1    = (const float*)d_in[9];
        W2    = (const float*)d_in[10];
        b2    = (const float*)d_in[11];
        Wsig  = (const float*)d_in[12];
        bsig  = (const float*)d_in[13];
        Wfeat = (const float*)d_in[14];
        bfeat = (const float*)d_in[15];
        Wc1   = (const float*)d_in[16];
        bc1   = (const float*)d_in[17];
        Wc2   = (const float*)d_in[18];
        bc2   = (const float*)d_in[19];
    }

    wfc_kernel<<<33, 256>>>(Wfeat, Wc1, bfeat, bc1);
    pack_kernel<<<29, 256>>>(W1, W2);               // also resets g_nchunks
    prep_kernel<<<NRAYS / 4, 256>>>(rays_d, Wc1, p2v);   // cv + chunk worklist
    mlp_kernel<<<NRAYS, 128>>>(pts, p2v, vox, Wpts, b1, b2,
                               Wsig, bsig, Wc2, bc2);
    render_kernel<<<NRAYS / 8, 256>>>(t_vals, dists, p2v, (float*)d_out);
}

// round 15
// speedup vs baseline: 1.1503x; 1.1503x over previous
#include <cuda_runtime.h>
#include <cuda_fp16.h>
#include <math.h>

typedef unsigned int u32;

#define NRAYS 8192
#define NVOX  100000

__device__ float g_sigma[NRAYS * 64];
__device__ float g_rgb[NRAYS * 64 * 3];
__device__ float g_cv[NRAYS * 64];
__device__ int   g_chunks[NRAYS * 4];    // 16-sample window ids: ray*4 + wi
__device__ int   g_nchunks;
__device__ float g_Wfc[128 * 64];   // Wfeat @ Wc1[:128]  (fused feat+color weight)
__device__ float g_cvc[64];         // bc1 + bfeat @ Wc1[:128]

// pre-packed B fragments: per (ks, nc, lane) a uint4 {b0h, b1h, b0l, b1l} (fp16 pairs)
__device__ uint4 g_fW1[2 * 16 * 32];    // 32->128
__device__ uint4 g_fW2[8 * 16 * 32];    // 128->128
__device__ uint4 g_fWC[8 * 8 * 32];     // 128->64 (fused Wfc)

__device__ __forceinline__ u32 sa(const void* p) {
    return (u32)__cvta_generic_to_shared(p);
}
__device__ __forceinline__ void ldsm4(u32* r, u32 addr) {
    asm volatile("ldmatrix.sync.aligned.m8n8.x4.shared.b16 {%0,%1,%2,%3}, [%4];"
        : "=r"(r[0]), "=r"(r[1]), "=r"(r[2]), "=r"(r[3]) : "r"(addr));
}
__device__ __forceinline__ void mma16816(float* d, const u32* a, const u32* b) {
    asm volatile(
        "mma.sync.aligned.m16n8k16.row.col.f32.f16.f16.f32 "
        "{%0,%1,%2,%3}, {%4,%5,%6,%7}, {%8,%9}, {%0,%1,%2,%3};"
        : "+f"(d[0]), "+f"(d[1]), "+f"(d[2]), "+f"(d[3])
        : "r"(a[0]), "r"(a[1]), "r"(a[2]), "r"(a[3]), "r"(b[0]), "r"(b[1]));
}
__device__ __forceinline__ u32 pkhf(float lo, float hi) {   // low half = lo
    u32 r;
    asm("{\n\t.reg .b16 h0, h1;\n\t"
        "cvt.rn.f16.f32 h0, %1;\n\t"
        "cvt.rn.f16.f32 h1, %2;\n\t"
        "mov.b32 %0, {h0, h1};\n\t}"
        : "=r"(r) : "f"(lo), "f"(hi));
    return r;
}

// M=64 MMA layer: A (fp16 plane, swizzled rows, byte stride astride) x prepacked B
// frags (hi+lo). acc layout: [mt*NCW + c][4], mt = 0..3 (16-row tiles).
template<int KS, int NCW>
__device__ __forceinline__ void do_layer64(u32 aP, int astride,
                                           const uint4* __restrict__ frag,
                                           int NCtot, int ncg0, int lane, float* acc)
{
    const int rit = (lane & 7) | (lane & 8);
    const int half = lane >> 4;
#pragma unroll
    for (int ks = 0; ks < KS; ks++) {
        const int u = ks * 2 + half;
        u32 a[4][4];
#pragma unroll
        for (int mt = 0; mt < 4; mt++) {
            const int r = mt * 16 + rit;
            ldsm4(a[mt], aP + r * astride + ((u ^ (r & 7)) << 4));
        }
#pragma unroll
        for (int c = 0; c < NCW; c++) {
            uint4 f = frag[(ks * NCtot + ncg0 + c) * 32 + lane];
            u32 bh[2] = {f.x, f.y}, bl[2] = {f.z, f.w};
#pragma unroll
            for (int mt = 0; mt < 4; mt++) {
                mma16816(acc + (mt * NCW + c) * 4, a[mt], bh);
                mma16816(acc + (mt * NCW + c) * 4, a[mt], bl);
            }
        }
    }
}

// epilogue: bias (+relu) (+sigma partials), fp16 pack, swizzled store, 64 rows
template<int NCW, bool RELU, bool SIG>
__device__ __forceinline__ void epi_act64(const float* acc, int ncg0,
                                          const float* __restrict__ bias,
                                          char* outP, int lane,
                                          const float* __restrict__ wsg, float* srow)
{
    const int g = lane >> 2, tq = lane & 3;
#pragma unroll
    for (int mt = 0; mt < 4; mt++) {
#pragma unroll
        for (int c = 0; c < NCW; c++) {
            const int ncg = ncg0 + c;
            const int c0 = ncg * 8 + 2 * tq;
            const float* a = acc + (mt * NCW + c) * 4;
            float x0 = a[0] + bias[c0], x1 = a[1] + bias[c0 + 1];
            float x2 = a[2] + bias[c0], x3 = a[3] + bias[c0 + 1];
            if (RELU) {
                x0 = fmaxf(x0, 0.f); x1 = fmaxf(x1, 0.f);
                x2 = fmaxf(x2, 0.f); x3 = fmaxf(x3, 0.f);
            }
            if (SIG) {
                srow[mt * 2 + 0] += x0 * wsg[c0] + x1 * wsg[c0 + 1];
                srow[mt * 2 + 1] += x2 * wsg[c0] + x3 * wsg[c0 + 1];
            }
            const int off0 = (mt * 16 + g) * 256 + ((ncg ^ g) << 4) + 4 * tq;
            const int off1 = (mt * 16 + g + 8) * 256 + ((ncg ^ g) << 4) + 4 * tq;
            *(u32*)(outP + off0) = pkhf(x0, x1);
            *(u32*)(outP + off1) = pkhf(x2, x3);
        }
    }
}

__global__ void __launch_bounds__(128, 4)
mlp_kernel(const float* __restrict__ pts, const int* __restrict__ p2v,
           const float* __restrict__ vox_emb, const float* __restrict__ Wpts,
           const float* __restrict__ b1, const float* __restrict__ b2,
           const float* __restrict__ Wsig, const float* __restrict__ bsig,
           const float* __restrict__ Wc2, const float* __restrict__ bc2)
{
    const int n = g_nchunks;
    const int tile = blockIdx.x;
    if (4 * tile >= n) return;

    // 4 independent 16-sample windows per tile (one per MMA m-tile)
    int cw[4], gW[4];
#pragma unroll
    for (int i = 0; i < 4; i++) {
        const int j = 4 * tile + i;
        cw[i] = g_chunks[j < n ? j : n - 1];       // tail: duplicate (benign rewrite)
        gW[i] = (cw[i] >> 2) * 64 + (cw[i] & 3) * 16;
    }

    const int t = threadIdx.x;
    const int w = t >> 5, lane = t & 31;
    const int g = lane >> 2, tq = lane & 3;

    // veP (64 rows x 128B = 8KB) aliases the front of bufB: ve's last reader is the
    // L1-layer MMA pass; bufB is first written by the L2 epilogue (after a sync).
    __shared__ __align__(16) char bufA[16384];   // 64 rows x 256B (fp16, 128 cols)
    __shared__ __align__(16) char bufB[16384];
    char* const veP = bufB;
    __shared__ float cv_sh[256];                 // per-window cv rows [win][64]
    __shared__ float b1s[128], b2s[128], wsg[128], wc2s[192], wps[96];
    __shared__ float bc2s[3], bsgs;
    __shared__ float sigp[4 * 64];
    __shared__ float rgbp[4 * 64 * 3];
    __shared__ int   idx_sh[64];
    __shared__ float pts_sh[192];                // [win][16 pts x 3]

    if (t < 128) { b1s[t] = b1[t]; b2s[t] = b2[t]; wsg[t] = Wsig[t]; }
    if (t < 96) wps[t] = Wpts[t];
    if (t < 64) { wc2s[t] = Wc2[t]; wc2s[64 + t] = Wc2[64 + t]; wc2s[128 + t] = Wc2[128 + t]; }
    if (t < 64) idx_sh[t] = p2v[gW[t >> 4] + (t & 15)];
    for (int e = t; e < 192; e += 128) pts_sh[e] = pts[gW[e / 48] * 3 + (e % 48)];
    for (int e = t; e < 256; e += 128) cv_sh[e] = g_cv[(cw[e >> 6] >> 2) * 64 + (e & 63)];
    if (t == 0) { bsgs = bsig[0]; bc2s[0] = bc2[0]; bc2s[1] = bc2[1]; bc2s[2] = bc2[2]; }
    __syncthreads();

    // ---- build ve: 64 rows (window = row>>4), fp16, swizzled ----
    {
#pragma unroll
        for (int pass = 0; pass < 2; pass++) {
            const int e = pass * 128 + t;          // e in [0,256): (row, q)
            const int row = e >> 2, q = e & 3;
            const int vi0 = idx_sh[row];
            const int vi = vi0 < 0 ? 0 : vi0;
            const float* ps = pts_sh + (row >> 4) * 48 + (row & 15) * 3;
            const float px = ps[0], py = ps[1], pz = ps[2];
            const float4* v4 = (const float4*)(vox_emb + (size_t)vi * 32 + q * 8);
            u32 hw[4];
#pragma unroll
            for (int i = 0; i < 2; i++) {
                float4 v = v4[i];
                const int k = q * 8 + i * 4;
                float x0 = v.x + px * wps[k]     + py * wps[32 + k]     + pz * wps[64 + k];
                float x1 = v.y + px * wps[k + 1] + py * wps[32 + k + 1] + pz * wps[64 + k + 1];
                float x2 = v.z + px * wps[k + 2] + py * wps[32 + k + 2] + pz * wps[64 + k + 2];
                float x3 = v.w + px * wps[k + 3] + py * wps[32 + k + 3] + pz * wps[64 + k + 3];
                hw[2 * i]     = pkhf(x0, x1);
                hw[2 * i + 1] = pkhf(x2, x3);
            }
            const int off = row * 128 + ((q ^ (row & 7)) << 4);
            *(uint4*)(veP + off) = make_uint4(hw[0], hw[1], hw[2], hw[3]);
        }
    }
    __syncthreads();

    const u32 veS = sa(veP);
    const u32 bAS = sa(bufA);
    const u32 bBS = sa(bufB);

    float acc[64];

    // ---- L1: 32 -> 128, relu ----
#pragma unroll
    for (int i = 0; i < 64; i++) acc[i] = 0.f;
    do_layer64<2, 4>(veS, 128, g_fW1, 16, 4 * w, lane, acc);
    epi_act64<4, true, false>(acc, 4 * w, b1s, bufA, lane, wsg, nullptr);
    __syncthreads();

    // ---- L2: 128 -> 128, relu, + sigma partials ----
#pragma unroll
    for (int i = 0; i < 64; i++) acc[i] = 0.f;
    do_layer64<8, 4>(bAS, 256, g_fW2, 16, 4 * w, lane, acc);
    {
        float srow[8] = {0.f, 0.f, 0.f, 0.f, 0.f, 0.f, 0.f, 0.f};
        epi_act64<4, true, true>(acc, 4 * w, b2s, bufB, lane, wsg, srow);
#pragma unroll
        for (int i = 0; i < 8; i++) {
            srow[i] += __shfl_xor_sync(0xffffffffu, srow[i], 1);
            srow[i] += __shfl_xor_sync(0xffffffffu, srow[i], 2);
        }
        if (tq == 0) {
#pragma unroll
            for (int mt = 0; mt < 4; mt++) {
                sigp[w * 64 + mt * 16 + g]     = srow[mt * 2 + 0];
                sigp[w * 64 + mt * 16 + 8 + g] = srow[mt * 2 + 1];
            }
        }
    }
    __syncthreads();
    if (t < 64) {
        const float s = sigp[t] + sigp[64 + t] + sigp[128 + t] + sigp[192 + t] + bsgs;
        g_sigma[gW[t >> 4] + (t & 15)] = s;
    }

    // ---- fused feat+color: h(bufB) @ Wfc -> 64 (+cv', relu), then rgb = c @ Wc2 ----
#pragma unroll
    for (int i = 0; i < 32; i++) acc[i] = 0.f;
    do_layer64<8, 2>(bBS, 256, g_fWC, 8, 2 * w, lane, acc);
    {
        float rr[24];
#pragma unroll
        for (int i = 0; i < 24; i++) rr[i] = 0.f;
#pragma unroll
        for (int mt = 0; mt < 4; mt++) {
            const int cvb = mt * 64;               // each m-tile is its own window
#pragma unroll
            for (int c = 0; c < 2; c++) {
                const int ncg = 2 * w + c;
                const int c0 = ncg * 8 + 2 * tq;
                const float* a = acc + (mt * 2 + c) * 4;
                float x0 = fmaxf(a[0] + cv_sh[cvb + c0], 0.f);
                float x1 = fmaxf(a[1] + cv_sh[cvb + c0 + 1], 0.f);
                float x2 = fmaxf(a[2] + cv_sh[cvb + c0], 0.f);
                float x3 = fmaxf(a[3] + cv_sh[cvb + c0 + 1], 0.f);
#pragma unroll
                for (int ch = 0; ch < 3; ch++) {
                    rr[(mt * 2 + 0) * 3 + ch] += x0 * wc2s[c0 * 3 + ch] + x1 * wc2s[(c0 + 1) * 3 + ch];
                    rr[(mt * 2 + 1) * 3 + ch] += x2 * wc2s[c0 * 3 + ch] + x3 * wc2s[(c0 + 1) * 3 + ch];
                }
            }
        }
#pragma unroll
        for (int i = 0; i < 24; i++) {
            rr[i] += __shfl_xor_sync(0xffffffffu, rr[i], 1);
            rr[i] += __shfl_xor_sync(0xffffffffu, rr[i], 2);
        }
        if (tq == 0) {
#pragma unroll
            for (int mt = 0; mt < 4; mt++) {
                const int r0 = mt * 16 + g, r1 = mt * 16 + 8 + g;
#pragma unroll
                for (int ch = 0; ch < 3; ch++) {
                    rgbp[w * 192 + r0 * 3 + ch] = rr[(mt * 2 + 0) * 3 + ch];
                    rgbp[w * 192 + r1 * 3 + ch] = rr[(mt * 2 + 1) * 3 + ch];
                }
            }
        }
    }
    __syncthreads();
    {
        for (int e = t; e < 192; e += 128) {
            const int row = e / 3, ch = e - row * 3;
            const float v = rgbp[row * 3 + ch] + rgbp[192 + row * 3 + ch]
                          + rgbp[384 + row * 3 + ch] + rgbp[576 + row * 3 + ch] + bc2s[ch];
            g_rgb[(gW[row >> 4] + (row & 15)) * 3 + ch] = v;
        }
    }
}

// fuse feat into color: Wfc = Wfeat @ Wc1[:128]  and  g_cvc = bc1 + bfeat @ Wc1[:128]
__global__ void wfc_kernel(const float* __restrict__ Wfeat, const float* __restrict__ Wc1,
                           const float* __restrict__ bfeat, const float* __restrict__ bc1)
{
    const int e = blockIdx.x * 256 + threadIdx.x;
    if (e < 8192) {
        const int k = e >> 6, n = e & 63;
        float s = 0.f;
#pragma unroll 8
        for (int j = 0; j < 128; j++) s += Wfeat[k * 128 + j] * Wc1[j * 64 + n];
        g_Wfc[k * 64 + n] = s;
    } else if (e < 8256) {
        const int n = e - 8192;
        float s = bc1[n];
#pragma unroll 8
        for (int j = 0; j < 128; j++) s += bfeat[j] * Wc1[j * 64 + n];
        g_cvc[n] = s;
    }
}

// one entry per 16-sample window whose FIRST sample is valid (valid is a prefix)
__global__ void build_kernel(const int* __restrict__ p2v)
{
    const int ray = blockIdx.x * 256 + threadIdx.x;
    if (ray >= NRAYS) return;
#pragma unroll
    for (int wi = 0; wi < 4; wi++) {
        if (p2v[ray * 64 + wi * 16] >= 0) {
            int i = atomicAdd(&g_nchunks, 1);
            g_chunks[i] = ray * 4 + wi;
        }
    }
}

// per-ray view PE -> cv[ray][64] = g_cvc + vemb @ Wc1[128:155]; 4 rays per block
__global__ void __launch_bounds__(256)
prep_kernel(const float* __restrict__ rays_d, const float* __restrict__ Wc1)
{
    __shared__ float ve[4][27];
    const int t = threadIdx.x;
    const int r = t >> 6, col = t & 63;
    const int ray = blockIdx.x * 4 + r;
    if (col < 27) {
        float dx = rays_d[ray * 3 + 0], dy = rays_d[ray * 3 + 1], dz = rays_d[ray * 3 + 2];
        float v;
        if (col == 0) v = dx;
        else if (col == 1) v = dy;
        else if (col == 2) v = dz;
        else {
            int u = col - 3;
            bool isc = (u >= 12);
            if (isc) u -= 12;
            int i = u >> 2, l = u & 3;
            float di = (i == 0) ? dx : ((i == 1) ? dy : dz);
            float a = di * (float)(1 << l);
            v = isc ? cosf(a) : sinf(a);
        }
        ve[r][col] = v;
    }
    __syncthreads();
    float s = g_cvc[col];
#pragma unroll
    for (int k = 0; k < 27; k++) s += Wc1[(128 + k) * 64 + col] * ve[r][k];
    g_cv[ray * 64 + col] = s;
}

// pack weight fragments (fp16 hi/lo) into mma B-operand order; also resets g_nchunks
__global__ void pack_kernel(const float* __restrict__ W1, const float* __restrict__ W2)
{
    int e = blockIdx.x * 256 + threadIdx.x;
    if (e == 7168) { g_nchunks = 0; return; }
    const float* W;
    uint4* dst;
    int N, NCtot, idx;
    if (e < 1024)      { W = W1;    dst = g_fW1; N = 128; NCtot = 16; idx = e; }
    else if (e < 5120) { W = W2;    dst = g_fW2; N = 128; NCtot = 16; idx = e - 1024; }
    else if (e < 7168) { W = g_Wfc; dst = g_fWC; N = 64;  NCtot = 8;  idx = e - 5120; }
    else return;
    const int lane = idx & 31;
    const int nc = (idx >> 5) % NCtot;
    const int ks = idx / (32 * NCtot);
    const int n = nc * 8 + (lane >> 2);
    const int k0 = ks * 16 + 2 * (lane & 3);
    float w00 = W[k0 * N + n], w01 = W[(k0 + 1) * N + n];
    float w08 = W[(k0 + 8) * N + n], w09 = W[(k0 + 9) * N + n];
    __half h00 = __float2half_rn(w00), h01 = __float2half_rn(w01);
    __half h08 = __float2half_rn(w08), h09 = __float2half_rn(w09);
    u32 b0h = ((u32)__half_as_ushort(h01) << 16) | __half_as_ushort(h00);
    u32 b1h = ((u32)__half_as_ushort(h09) << 16) | __half_as_ushort(h08);
    u32 b0l = pkhf(w00 - __half2float(h00), w01 - __half2float(h01));
    u32 b1l = pkhf(w08 - __half2float(h08), w09 - __half2float(h09));
    dst[idx] = make_uint4(b0h, b1h, b0l, b1l);
}

// per-ray volumetric rendering: warp per ray, 2 samples per lane
__global__ void __launch_bounds__(256)
render_kernel(const float* __restrict__ t_vals, const float* __restrict__ dists,
              const int* __restrict__ p2v, float* __restrict__ out)
{
    int warp = threadIdx.x >> 5;
    int lane = threadIdx.x & 31;
    int ray = blockIdx.x * 8 + warp;
    if (ray >= NRAYS) return;
    int b = ray * 64;
    int i1 = b + lane, i2 = b + 32 + lane;

    bool m1 = p2v[i1] >= 0;
    bool m2 = p2v[i2] >= 0;
    float fe1 = m1 ? fmaxf(g_sigma[i1], 0.f) * dists[i1] : 0.f;
    float fe2 = m2 ? fmaxf(g_sigma[i2], 0.f) * dists[i2] : 0.f;

    float c1 = fe1;
#pragma unroll
    for (int d = 1; d < 32; d <<= 1) {
        float v = __shfl_up_sync(0xffffffffu, c1, d);
        if (lane >= d) c1 += v;
    }
    float tot = __shfl_sync(0xffffffffu, c1, 31);
    float c2 = fe2;
#pragma unroll
    for (int d = 1; d < 32; d <<= 1) {
        float v = __shfl_up_sync(0xffffffffu, c2, d);
        if (lane >= d) c2 += v;
    }
    c2 += tot;

    float T1 = expf(-(c1 - fe1));
    float T2 = expf(-(c2 - fe2));
    float w1 = (1.f - expf(-fe1)) * T1;
    float w2 = (1.f - expf(-fe2)) * T2;

    float r = 0.f, g = 0.f, bl = 0.f;
    if (m1) {
        float x = g_rgb[i1 * 3 + 0], y = g_rgb[i1 * 3 + 1], z = g_rgb[i1 * 3 + 2];
        r += w1 * (0.5f * x + 0.5f);
        g += w1 * (0.5f * y + 0.5f);
        bl += w1 * (0.5f * z + 0.5f);
    }
    if (m2) {
        float x = g_rgb[i2 * 3 + 0], y = g_rgb[i2 * 3 + 1], z = g_rgb[i2 * 3 + 2];
        r += w2 * (0.5f * x + 0.5f);
        g += w2 * (0.5f * y + 0.5f);
        bl += w2 * (0.5f * z + 0.5f);
    }
    float aw = w1 + w2;
    float dp = w1 * t_vals[i1] + w2 * t_vals[i2];

#pragma unroll
    for (int d = 16; d; d >>= 1) {
        r  += __shfl_down_sync(0xffffffffu, r, d);
        g  += __shfl_down_sync(0xffffffffu, g, d);
        bl += __shfl_down_sync(0xffffffffu, bl, d);
        aw += __shfl_down_sync(0xffffffffu, aw, d);
        dp += __shfl_down_sync(0xffffffffu, dp, d);
    }
    if (lane == 0) {
        bool hit = p2v[b] >= 0;
        float disp = hit ? 1.f / fmaxf(1e-10f, dp / fmaxf(aw, 1e-10f)) : 0.f;
        out[ray * 3 + 0] = hit ? r : 0.f;
        out[ray * 3 + 1] = hit ? g : 0.f;
        out[ray * 3 + 2] = hit ? bl : 0.f;
        out[NRAYS * 3 + ray] = disp;
        out[NRAYS * 4 + ray] = hit ? aw : 0.f;
    }
}

extern "C" void kernel_launch(void* const* d_in, const int* in_sizes, int n_in,
                              void* d_out, int out_size)
{
    const float* rays_d = (const float*)d_in[0];
    const float* pts    = (const float*)d_in[1];
    const float* t_vals = (const float*)d_in[2];
    const float* dists  = (const float*)d_in[3];
    const int* p2v;
    const float *vox, *Wpts, *W1, *b1, *W2, *b2, *Wsig, *bsig, *Wfeat, *bfeat,
                *Wc1, *bc1, *Wc2, *bc2;

    if (in_sizes[4] == NVOX * 32) {
        vox   = (const float*)d_in[4];
        Wpts  = (const float*)d_in[5];
        W1    = (const float*)d_in[6];
        b1    = (const float*)d_in[7];
        W2    = (const float*)d_in[8];
        b2    = (const float*)d_in[9];
        Wsig  = (const float*)d_in[10];
        bsig  = (const float*)d_in[11];
        Wfeat = (const float*)d_in[12];
        bfeat = (const float*)d_in[13];
        Wc1   = (const float*)d_in[14];
        bc1   = (const float*)d_in[15];
        Wc2   = (const float*)d_in[16];
        bc2   = (const float*)d_in[17];
        p2v   = (const int*)d_in[18];
    } else {
        p2v   = (const int*)d_in[4];
        vox   = (const float*)d_in[6];
        Wpts  = (const float*)d_in[7];
        W1    = (const float*)d_in[8];
        b1    = (const float*)d_in[9];
        W2    = (const float*)d_in[10];
        b2    = (const float*)d_in[11];
        Wsig  = (const float*)d_in[12];
        bsig  = (const float*)d_in[13];
        Wfeat = (const float*)d_in[14];
        bfeat = (const float*)d_in[15];
        Wc1   = (const float*)d_in[16];
        bc1   = (const float*)d_in[17];
        Wc2   = (const float*)d_in[18];
        bc2   = (const float*)d_in[19];
    }

    wfc_kernel<<<33, 256>>>(Wfeat, Wc1, bfeat, bc1);
    pack_kernel<<<29, 256>>>(W1, W2);               // also resets g_nchunks
    build_kernel<<<NRAYS / 256, 256>>>(p2v);
    prep_kernel<<<NRAYS / 4, 256>>>(rays_d, Wc1);
    mlp_kernel<<<NRAYS, 128>>>(pts, p2v, vox, Wpts, b1, b2,
                               Wsig, bsig, Wc2, bc2);
    render_kernel<<<NRAYS / 8, 256>>>(t_vals, dists, p2v, (float*)d_out);
}

// round 16
// speedup vs baseline: 1.1948x; 1.0387x over previous
#include <cuda_runtime.h>
#include <cuda_fp16.h>
#include <math.h>

typedef unsigned int u32;

#define NRAYS 8192
#define NVOX  100000

__device__ float g_sigma[NRAYS * 64];
__device__ float g_rgb[NRAYS * 64 * 3];
__device__ float g_cv[NRAYS * 64];
__device__ int   g_chunks[NRAYS * 8];    // 8-sample window ids: ray*8 + wi
__device__ int   g_nchunks;
__device__ float g_Wfc[128 * 64];   // Wfeat @ Wc1[:128]  (fused feat+color weight)
__device__ float g_cvc[64];         // bc1 + bfeat @ Wc1[:128]

// pre-packed B fragments: per (ks, nc, lane) a uint4 {b0h, b1h, b0l, b1l} (fp16 pairs)
__device__ uint4 g_fW1[2 * 16 * 32];    // 32->128
__device__ uint4 g_fW2[8 * 16 * 32];    // 128->128
__device__ uint4 g_fWC[8 * 8 * 32];     // 128->64 (fused Wfc)

__device__ __forceinline__ u32 sa(const void* p) {
    return (u32)__cvta_generic_to_shared(p);
}
__device__ __forceinline__ void ldsm4(u32* r, u32 addr) {
    asm volatile("ldmatrix.sync.aligned.m8n8.x4.shared.b16 {%0,%1,%2,%3}, [%4];"
        : "=r"(r[0]), "=r"(r[1]), "=r"(r[2]), "=r"(r[3]) : "r"(addr));
}
__device__ __forceinline__ void mma16816(float* d, const u32* a, const u32* b) {
    asm volatile(
        "mma.sync.aligned.m16n8k16.row.col.f32.f16.f16.f32 "
        "{%0,%1,%2,%3}, {%4,%5,%6,%7}, {%8,%9}, {%0,%1,%2,%3};"
        : "+f"(d[0]), "+f"(d[1]), "+f"(d[2]), "+f"(d[3])
        : "r"(a[0]), "r"(a[1]), "r"(a[2]), "r"(a[3]), "r"(b[0]), "r"(b[1]));
}
__device__ __forceinline__ u32 pkhf(float lo, float hi) {   // low half = lo
    u32 r;
    asm("{\n\t.reg .b16 h0, h1;\n\t"
        "cvt.rn.f16.f32 h0, %1;\n\t"
        "cvt.rn.f16.f32 h1, %2;\n\t"
        "mov.b32 %0, {h0, h1};\n\t}"
        : "=r"(r) : "f"(lo), "f"(hi));
    return r;
}

// M=64 MMA layer: A (fp16 plane, swizzled rows, byte stride astride) x prepacked B
// frags (hi+lo). acc layout: [mt*NCW + c][4], mt = 0..3 (16-row tiles).
template<int KS, int NCW>
__device__ __forceinline__ void do_layer64(u32 aP, int astride,
                                           const uint4* __restrict__ frag,
                                           int NCtot, int ncg0, int lane, float* acc)
{
    const int rit = (lane & 7) | (lane & 8);
    const int half = lane >> 4;
#pragma unroll
    for (int ks = 0; ks < KS; ks++) {
        const int u = ks * 2 + half;
        u32 a[4][4];
#pragma unroll
        for (int mt = 0; mt < 4; mt++) {
            const int r = mt * 16 + rit;
            ldsm4(a[mt], aP + r * astride + ((u ^ (r & 7)) << 4));
        }
#pragma unroll
        for (int c = 0; c < NCW; c++) {
            uint4 f = frag[(ks * NCtot + ncg0 + c) * 32 + lane];
            u32 bh[2] = {f.x, f.y}, bl[2] = {f.z, f.w};
#pragma unroll
            for (int mt = 0; mt < 4; mt++) {
                mma16816(acc + (mt * NCW + c) * 4, a[mt], bh);
                mma16816(acc + (mt * NCW + c) * 4, a[mt], bl);
            }
        }
    }
}

// epilogue: bias (+relu) (+sigma partials), fp16 pack, swizzled store, 64 rows
template<int NCW, bool RELU, bool SIG>
__device__ __forceinline__ void epi_act64(const float* acc, int ncg0,
                                          const float* __restrict__ bias,
                                          char* outP, int lane,
                                          const float* __restrict__ wsg, float* srow)
{
    const int g = lane >> 2, tq = lane & 3;
#pragma unroll
    for (int mt = 0; mt < 4; mt++) {
#pragma unroll
        for (int c = 0; c < NCW; c++) {
            const int ncg = ncg0 + c;
            const int c0 = ncg * 8 + 2 * tq;
            const float* a = acc + (mt * NCW + c) * 4;
            float x0 = a[0] + bias[c0], x1 = a[1] + bias[c0 + 1];
            float x2 = a[2] + bias[c0], x3 = a[3] + bias[c0 + 1];
            if (RELU) {
                x0 = fmaxf(x0, 0.f); x1 = fmaxf(x1, 0.f);
                x2 = fmaxf(x2, 0.f); x3 = fmaxf(x3, 0.f);
            }
            if (SIG) {
                srow[mt * 2 + 0] += x0 * wsg[c0] + x1 * wsg[c0 + 1];
                srow[mt * 2 + 1] += x2 * wsg[c0] + x3 * wsg[c0 + 1];
            }
            const int off0 = (mt * 16 + g) * 256 + ((ncg ^ g) << 4) + 4 * tq;
            const int off1 = (mt * 16 + g + 8) * 256 + ((ncg ^ g) << 4) + 4 * tq;
            *(u32*)(outP + off0) = pkhf(x0, x1);
            *(u32*)(outP + off1) = pkhf(x2, x3);
        }
    }
}

__global__ void __launch_bounds__(128, 4)
mlp_kernel(const float* __restrict__ pts, const int* __restrict__ p2v,
           const float* __restrict__ vox_emb, const float* __restrict__ Wpts,
           const float* __restrict__ b1, const float* __restrict__ b2,
           const float* __restrict__ Wsig, const float* __restrict__ bsig,
           const float* __restrict__ Wc2, const float* __restrict__ bc2)
{
    const int n = g_nchunks;
    const int tile = blockIdx.x;
    if (8 * tile >= n) return;

    // 8 independent 8-sample windows per tile (two per MMA m-tile)
    int cw[8], gW[8];
#pragma unroll
    for (int i = 0; i < 8; i++) {
        const int j = 8 * tile + i;
        cw[i] = g_chunks[j < n ? j : n - 1];       // tail: duplicate (benign rewrite)
        gW[i] = (cw[i] >> 3) * 64 + (cw[i] & 7) * 8;
    }

    const int t = threadIdx.x;
    const int w = t >> 5, lane = t & 31;
    const int g = lane >> 2, tq = lane & 3;

    // veP (64 rows x 128B = 8KB) aliases the front of bufB: ve's last reader is the
    // L1-layer MMA pass; bufB is first written by the L2 epilogue (after a sync).
    __shared__ __align__(16) char bufA[16384];   // 64 rows x 256B (fp16, 128 cols)
    __shared__ __align__(16) char bufB[16384];
    char* const veP = bufB;
    __shared__ float cv_sh[512];                 // per-window cv rows [win][64]
    __shared__ float b1s[128], b2s[128], wsg[128], wc2s[192], wps[96];
    __shared__ float bc2s[3], bsgs;
    __shared__ float sigp[4 * 64];
    __shared__ float rgbp[4 * 64 * 3];
    __shared__ int   idx_sh[64];
    __shared__ float pts_sh[192];                // [win][8 pts x 3]

    if (t < 128) { b1s[t] = b1[t]; b2s[t] = b2[t]; wsg[t] = Wsig[t]; }
    if (t < 96) wps[t] = Wpts[t];
    if (t < 64) { wc2s[t] = Wc2[t]; wc2s[64 + t] = Wc2[64 + t]; wc2s[128 + t] = Wc2[128 + t]; }
    if (t < 64) idx_sh[t] = p2v[gW[t >> 3] + (t & 7)];
    for (int e = t; e < 192; e += 128) pts_sh[e] = pts[gW[e / 24] * 3 + (e % 24)];
    for (int e = t; e < 512; e += 128) cv_sh[e] = g_cv[(cw[e >> 6] >> 3) * 64 + (e & 63)];
    if (t == 0) { bsgs = bsig[0]; bc2s[0] = bc2[0]; bc2s[1] = bc2[1]; bc2s[2] = bc2[2]; }
    __syncthreads();

    // ---- build ve: 64 rows (window = row>>3), fp16, swizzled ----
    {
#pragma unroll
        for (int pass = 0; pass < 2; pass++) {
            const int e = pass * 128 + t;          // e in [0,256): (row, q)
            const int row = e >> 2, q = e & 3;
            const int vi0 = idx_sh[row];
            const int vi = vi0 < 0 ? 0 : vi0;
            const float* ps = pts_sh + (row >> 3) * 24 + (row & 7) * 3;
            const float px = ps[0], py = ps[1], pz = ps[2];
            const float4* v4 = (const float4*)(vox_emb + (size_t)vi * 32 + q * 8);
            u32 hw[4];
#pragma unroll
            for (int i = 0; i < 2; i++) {
                float4 v = v4[i];
                const int k = q * 8 + i * 4;
                float x0 = v.x + px * wps[k]     + py * wps[32 + k]     + pz * wps[64 + k];
                float x1 = v.y + px * wps[k + 1] + py * wps[32 + k + 1] + pz * wps[64 + k + 1];
                float x2 = v.z + px * wps[k + 2] + py * wps[32 + k + 2] + pz * wps[64 + k + 2];
                float x3 = v.w + px * wps[k + 3] + py * wps[32 + k + 3] + pz * wps[64 + k + 3];
                hw[2 * i]     = pkhf(x0, x1);
                hw[2 * i + 1] = pkhf(x2, x3);
            }
            const int off = row * 128 + ((q ^ (row & 7)) << 4);
            *(uint4*)(veP + off) = make_uint4(hw[0], hw[1], hw[2], hw[3]);
        }
    }
    __syncthreads();

    const u32 veS = sa(veP);
    const u32 bAS = sa(bufA);
    const u32 bBS = sa(bufB);

    float acc[64];

    // ---- L1: 32 -> 128, relu ----
#pragma unroll
    for (int i = 0; i < 64; i++) acc[i] = 0.f;
    do_layer64<2, 4>(veS, 128, g_fW1, 16, 4 * w, lane, acc);
    epi_act64<4, true, false>(acc, 4 * w, b1s, bufA, lane, wsg, nullptr);
    __syncthreads();

    // ---- L2: 128 -> 128, relu, + sigma partials ----
#pragma unroll
    for (int i = 0; i < 64; i++) acc[i] = 0.f;
    do_layer64<8, 4>(bAS, 256, g_fW2, 16, 4 * w, lane, acc);
    {
        float srow[8] = {0.f, 0.f, 0.f, 0.f, 0.f, 0.f, 0.f, 0.f};
        epi_act64<4, true, true>(acc, 4 * w, b2s, bufB, lane, wsg, srow);
#pragma unroll
        for (int i = 0; i < 8; i++) {
            srow[i] += __shfl_xor_sync(0xffffffffu, srow[i], 1);
            srow[i] += __shfl_xor_sync(0xffffffffu, srow[i], 2);
        }
        if (tq == 0) {
#pragma unroll
            for (int mt = 0; mt < 4; mt++) {
                sigp[w * 64 + mt * 16 + g]     = srow[mt * 2 + 0];
                sigp[w * 64 + mt * 16 + 8 + g] = srow[mt * 2 + 1];
            }
        }
    }
    __syncthreads();
    if (t < 64) {
        const float s = sigp[t] + sigp[64 + t] + sigp[128 + t] + sigp[192 + t] + bsgs;
        g_sigma[gW[t >> 3] + (t & 7)] = s;
    }

    // ---- fused feat+color: h(bufB) @ Wfc -> 64 (+cv', relu), then rgb = c @ Wc2 ----
#pragma unroll
    for (int i = 0; i < 32; i++) acc[i] = 0.f;
    do_layer64<8, 2>(bBS, 256, g_fWC, 8, 2 * w, lane, acc);
    {
        float rr[24];
#pragma unroll
        for (int i = 0; i < 24; i++) rr[i] = 0.f;
#pragma unroll
        for (int mt = 0; mt < 4; mt++) {
            // rows mt*16+g (a[0],a[1]) -> window 2*mt; rows mt*16+8+g (a[2],a[3]) -> 2*mt+1
            const int cv0 = (2 * mt) * 64, cv1 = (2 * mt + 1) * 64;
#pragma unroll
            for (int c = 0; c < 2; c++) {
                const int ncg = 2 * w + c;
                const int c0 = ncg * 8 + 2 * tq;
                const float* a = acc + (mt * 2 + c) * 4;
                float x0 = fmaxf(a[0] + cv_sh[cv0 + c0], 0.f);
                float x1 = fmaxf(a[1] + cv_sh[cv0 + c0 + 1], 0.f);
                float x2 = fmaxf(a[2] + cv_sh[cv1 + c0], 0.f);
                float x3 = fmaxf(a[3] + cv_sh[cv1 + c0 + 1], 0.f);
#pragma unroll
                for (int ch = 0; ch < 3; ch++) {
                    rr[(mt * 2 + 0) * 3 + ch] += x0 * wc2s[c0 * 3 + ch] + x1 * wc2s[(c0 + 1) * 3 + ch];
                    rr[(mt * 2 + 1) * 3 + ch] += x2 * wc2s[c0 * 3 + ch] + x3 * wc2s[(c0 + 1) * 3 + ch];
                }
            }
        }
#pragma unroll
        for (int i = 0; i < 24; i++) {
            rr[i] += __shfl_xor_sync(0xffffffffu, rr[i], 1);
            rr[i] += __shfl_xor_sync(0xffffffffu, rr[i], 2);
        }
        if (tq == 0) {
#pragma unroll
            for (int mt = 0; mt < 4; mt++) {
                const int r0 = mt * 16 + g, r1 = mt * 16 + 8 + g;
#pragma unroll
                for (int ch = 0; ch < 3; ch++) {
                    rgbp[w * 192 + r0 * 3 + ch] = rr[(mt * 2 + 0) * 3 + ch];
                    rgbp[w * 192 + r1 * 3 + ch] = rr[(mt * 2 + 1) * 3 + ch];
                }
            }
        }
    }
    __syncthreads();
    {
        for (int e = t; e < 192; e += 128) {
            const int row = e / 3, ch = e - row * 3;
            const float v = rgbp[row * 3 + ch] + rgbp[192 + row * 3 + ch]
                          + rgbp[384 + row * 3 + ch] + rgbp[576 + row * 3 + ch] + bc2s[ch];
            g_rgb[(gW[row >> 3] + (row & 7)) * 3 + ch] = v;
        }
    }
}

// fuse feat into color: Wfc = Wfeat @ Wc1[:128]  and  g_cvc = bc1 + bfeat @ Wc1[:128]
__global__ void wfc_kernel(const float* __restrict__ Wfeat, const float* __restrict__ Wc1,
                           const float* __restrict__ bfeat, const float* __restrict__ bc1)
{
    const int e = blockIdx.x * 256 + threadIdx.x;
    if (e < 8192) {
        const int k = e >> 6, n = e & 63;
        float s = 0.f;
#pragma unroll 8
        for (int j = 0; j < 128; j++) s += Wfeat[k * 128 + j] * Wc1[j * 64 + n];
        g_Wfc[k * 64 + n] = s;
    } else if (e < 8256) {
        const int n = e - 8192;
        float s = bc1[n];
#pragma unroll 8
        for (int j = 0; j < 128; j++) s += bfeat[j] * Wc1[j * 64 + n];
        g_cvc[n] = s;
    }
}

// one entry per 8-sample window whose FIRST sample is valid (valid is a prefix)
__global__ void build_kernel(const int* __restrict__ p2v)
{
    const int ray = blockIdx.x * 256 + threadIdx.x;
    if (ray >= NRAYS) return;
#pragma unroll
    for (int wi = 0; wi < 8; wi++) {
        if (p2v[ray * 64 + wi * 8] >= 0) {
            int i = atomicAdd(&g_nchunks, 1);
            g_chunks[i] = ray * 8 + wi;
        }
    }
}

// per-ray view PE -> cv[ray][64] = g_cvc + vemb @ Wc1[128:155]; 4 rays per block
__global__ void __launch_bounds__(256)
prep_kernel(const float* __restrict__ rays_d, const float* __restrict__ Wc1)
{
    __shared__ float ve[4][27];
    const int t = threadIdx.x;
    const int r = t >> 6, col = t & 63;
    const int ray = blockIdx.x * 4 + r;
    if (col < 27) {
        float dx = rays_d[ray * 3 + 0], dy = rays_d[ray * 3 + 1], dz = rays_d[ray * 3 + 2];
        float v;
        if (col == 0) v = dx;
        else if (col == 1) v = dy;
        else if (col == 2) v = dz;
        else {
            int u = col - 3;
            bool isc = (u >= 12);
            if (isc) u -= 12;
            int i = u >> 2, l = u & 3;
            float di = (i == 0) ? dx : ((i == 1) ? dy : dz);
            float a = di * (float)(1 << l);
            v = isc ? __cosf(a) : __sinf(a);   // |a| <= 8: intrinsic abs err ~1e-5
        }
        ve[r][col] = v;
    }
    __syncthreads();
    float s = g_cvc[col];
#pragma unroll
    for (int k = 0; k < 27; k++) s += Wc1[(128 + k) * 64 + col] * ve[r][k];
    g_cv[ray * 64 + col] = s;
}

// pack weight fragments (fp16 hi/lo) into mma B-operand order; also resets g_nchunks
__global__ void pack_kernel(const float* __restrict__ W1, const float* __restrict__ W2)
{
    int e = blockIdx.x * 256 + threadIdx.x;
    if (e == 7168) { g_nchunks = 0; return; }
    const float* W;
    uint4* dst;
    int N, NCtot, idx;
    if (e < 1024)      { W = W1;    dst = g_fW1; N = 128; NCtot = 16; idx = e; }
    else if (e < 5120) { W = W2;    dst = g_fW2; N = 128; NCtot = 16; idx = e - 1024; }
    else if (e < 7168) { W = g_Wfc; dst = g_fWC; N = 64;  NCtot = 8;  idx = e - 5120; }
    else return;
    const int lane = idx & 31;
    const int nc = (idx >> 5) % NCtot;
    const int ks = idx / (32 * NCtot);
    const int n = nc * 8 + (lane >> 2);
    const int k0 = ks * 16 + 2 * (lane & 3);
    float w00 = W[k0 * N + n], w01 = W[(k0 + 1) * N + n];
    float w08 = W[(k0 + 8) * N + n], w09 = W[(k0 + 9) * N + n];
    __half h00 = __float2half_rn(w00), h01 = __float2half_rn(w01);
    __half h08 = __float2half_rn(w08), h09 = __float2half_rn(w09);
    u32 b0h = ((u32)__half_as_ushort(h01) << 16) | __half_as_ushort(h00);
    u32 b1h = ((u32)__half_as_ushort(h09) << 16) | __half_as_ushort(h08);
    u32 b0l = pkhf(w00 - __half2float(h00), w01 - __half2float(h01));
    u32 b1l = pkhf(w08 - __half2float(h08), w09 - __half2float(h09));
    dst[idx] = make_uint4(b0h, b1h, b0l, b1l);
}

// per-ray volumetric rendering: warp per ray, 2 samples per lane
__global__ void __launch_bounds__(256)
render_kernel(const float* __restrict__ t_vals, const float* __restrict__ dists,
              const int* __restrict__ p2v, float* __restrict__ out)
{
    int warp = threadIdx.x >> 5;
    int lane = threadIdx.x & 31;
    int ray = blockIdx.x * 8 + warp;
    if (ray >= NRAYS) return;
    int b = ray * 64;
    int i1 = b + lane, i2 = b + 32 + lane;

    bool m1 = p2v[i1] >= 0;
    bool m2 = p2v[i2] >= 0;
    float fe1 = m1 ? fmaxf(g_sigma[i1], 0.f) * dists[i1] : 0.f;
    float fe2 = m2 ? fmaxf(g_sigma[i2], 0.f) * dists[i2] : 0.f;

    float c1 = fe1;
#pragma unroll
    for (int d = 1; d < 32; d <<= 1) {
        float v = __shfl_up_sync(0xffffffffu, c1, d);
        if (lane >= d) c1 += v;
    }
    float tot = __shfl_sync(0xffffffffu, c1, 31);
    float c2 = fe2;
#pragma unroll
    for (int d = 1; d < 32; d <<= 1) {
        float v = __shfl_up_sync(0xffffffffu, c2, d);
        if (lane >= d) c2 += v;
    }
    c2 += tot;

    float T1 = expf(-(c1 - fe1));
    float T2 = expf(-(c2 - fe2));
    float w1 = (1.f - expf(-fe1)) * T1;
    float w2 = (1.f - expf(-fe2)) * T2;

    float r = 0.f, g = 0.f, bl = 0.f;
    if (m1) {
        float x = g_rgb[i1 * 3 + 0], y = g_rgb[i1 * 3 + 1], z = g_rgb[i1 * 3 + 2];
        r += w1 * (0.5f * x + 0.5f);
        g += w1 * (0.5f * y + 0.5f);
        bl += w1 * (0.5f * z + 0.5f);
    }
    if (m2) {
        float x = g_rgb[i2 * 3 + 0], y = g_rgb[i2 * 3 + 1], z = g_rgb[i2 * 3 + 2];
        r += w2 * (0.5f * x + 0.5f);
        g += w2 * (0.5f * y + 0.5f);
        bl += w2 * (0.5f * z + 0.5f);
    }
    float aw = w1 + w2;
    float dp = w1 * t_vals[i1] + w2 * t_vals[i2];

#pragma unroll
    for (int d = 16; d; d >>= 1) {
        r  += __shfl_down_sync(0xffffffffu, r, d);
        g  += __shfl_down_sync(0xffffffffu, g, d);
        bl += __shfl_down_sync(0xffffffffu, bl, d);
        aw += __shfl_down_sync(0xffffffffu, aw, d);
        dp += __shfl_down_sync(0xffffffffu, dp, d);
    }
    if (lane == 0) {
        bool hit = p2v[b] >= 0;
        float disp = hit ? 1.f / fmaxf(1e-10f, dp / fmaxf(aw, 1e-10f)) : 0.f;
        out[ray * 3 + 0] = hit ? r : 0.f;
        out[ray * 3 + 1] = hit ? g : 0.f;
        out[ray * 3 + 2] = hit ? bl : 0.f;
        out[NRAYS * 3 + ray] = disp;
        out[NRAYS * 4 + ray] = hit ? aw : 0.f;
    }
}

extern "C" void kernel_launch(void* const* d_in, const int* in_sizes, int n_in,
                              void* d_out, int out_size)
{
    const float* rays_d = (const float*)d_in[0];
    const float* pts    = (const float*)d_in[1];
    const float* t_vals = (const float*)d_in[2];
    const float* dists  = (const float*)d_in[3];
    const int* p2v;
    const float *vox, *Wpts, *W1, *b1, *W2, *b2, *Wsig, *bsig, *Wfeat, *bfeat,
                *Wc1, *bc1, *Wc2, *bc2;

    if (in_sizes[4] == NVOX * 32) {
        vox   = (const float*)d_in[4];
        Wpts  = (const float*)d_in[5];
        W1    = (const float*)d_in[6];
        b1    = (const float*)d_in[7];
        W2    = (const float*)d_in[8];
        b2    = (const float*)d_in[9];
        Wsig  = (const float*)d_in[10];
        bsig  = (const float*)d_in[11];
        Wfeat = (const float*)d_in[12];
        bfeat = (const float*)d_in[13];
        Wc1   = (const float*)d_in[14];
        bc1   = (const float*)d_in[15];
        Wc2   = (const float*)d_in[16];
        bc2   = (const float*)d_in[17];
        p2v   = (const int*)d_in[18];
    } else {
        p2v   = (const int*)d_in[4];
        vox   = (const float*)d_in[6];
        Wpts  = (const float*)d_in[7];
        W1    = (const float*)d_in[8];
        b1    = (const float*)d_in[9];
        W2    = (const float*)d_in[10];
        b2    = (const float*)d_in[11];
        Wsig  = (const float*)d_in[12];
        bsig  = (const float*)d_in[13];
        Wfeat = (const float*)d_in[14];
        bfeat = (const float*)d_in[15];
        Wc1   = (const float*)d_in[16];
        bc1   = (const float*)d_in[17];
        Wc2   = (const float*)d_in[18];
        bc2   = (const float*)d_in[19];
    }

    wfc_kernel<<<33, 256>>>(Wfeat, Wc1, bfeat, bc1);
    pack_kernel<<<29, 256>>>(W1, W2);               // also resets g_nchunks
    build_kernel<<<NRAYS / 256, 256>>>(p2v);
    prep_kernel<<<NRAYS / 4, 256>>>(rays_d, Wc1);
    mlp_kernel<<<NRAYS, 128>>>(pts, p2v, vox, Wpts, b1, b2,
                               Wsig, bsig, Wc2, bc2);
    render_kernel<<<NRAYS / 8, 256>>>(t_vals, dists, p2v, (float*)d_out);
}